// round 1
// baseline (speedup 1.0000x reference)
#include <cuda_runtime.h>
#include <cuda_bf16.h>
#include <cstddef>
#include <cstdint>

// Problem constants (fixed-shape bench)
// y:    [2, 2048, 1024] fp32
// Wqkv: [1024, 3072]    fp32
// Wff:  [1024, 1024]    fp32
// bff:  [1024]          fp32
// out:  [2, 2048, 1024] fp32

#define SEQ 2048
#define NIN 1024
#define NOUT 1024
#define NH 16
#define HD 64

// Scratch (device globals: allocation-free per harness rules)
__device__ float g_qkv[4096 * 3 * 1024];   // 48 MB: [b*n, 3*1024], col = which*1024 + h*64 + d
__device__ float g_ctx[4096 * 1024];       // 16 MB: [b*n, 1024],  col = h*64 + d

// ---------------------------------------------------------------------------
// SGEMM: C[M,N] = A[M,K] @ B[K,N] (+ bias[N]); 128x128x16 tiles, 8x8/thread
// ---------------------------------------------------------------------------
__global__ void __launch_bounds__(256) sgemm128(
    const float* __restrict__ A, const float* __restrict__ B,
    const float* __restrict__ bias, float* __restrict__ C,
    int M, int N, int K)
{
    const int BM = 128, BN = 128, BK = 16;
    __shared__ float As[BK][BM];
    __shared__ float Bs[BK][BN];

    int t  = threadIdx.x;          // 0..255
    int tx = t & 15;               // 0..15 -> 8 cols each
    int ty = t >> 4;               // 0..15 -> 8 rows each
    int bm = blockIdx.y * BM;
    int bn = blockIdx.x * BN;

    float acc[8][8];
    #pragma unroll
    for (int m = 0; m < 8; m++)
        #pragma unroll
        for (int n = 0; n < 8; n++) acc[m][n] = 0.f;

    for (int k0 = 0; k0 < K; k0 += BK) {
        // Load tiles: 2048 floats each = 512 float4; 256 threads x 2
        #pragma unroll
        for (int i = 0; i < 2; i++) {
            int idx = t + i * 256;
            // A tile: row-major -> store transposed As[k][row]
            int arow = idx >> 2;           // 4 float4 per row (BK=16)
            int ak4  = idx & 3;
            float4 a = *(const float4*)(A + (size_t)(bm + arow) * K + k0 + ak4 * 4);
            As[ak4 * 4 + 0][arow] = a.x;
            As[ak4 * 4 + 1][arow] = a.y;
            As[ak4 * 4 + 2][arow] = a.z;
            As[ak4 * 4 + 3][arow] = a.w;
            // B tile: row-major [BK][BN]
            int brow = idx >> 5;           // 32 float4 per row (BN=128)
            int bc4  = idx & 31;
            *(float4*)&Bs[brow][bc4 * 4] =
                *(const float4*)(B + (size_t)(k0 + brow) * N + bn + bc4 * 4);
        }
        __syncthreads();

        #pragma unroll
        for (int kk = 0; kk < BK; kk++) {
            float ra[8], rb[8];
            #pragma unroll
            for (int m = 0; m < 8; m++) ra[m] = As[kk][ty * 8 + m];
            #pragma unroll
            for (int n = 0; n < 8; n++) rb[n] = Bs[kk][tx * 8 + n];
            #pragma unroll
            for (int m = 0; m < 8; m++)
                #pragma unroll
                for (int n = 0; n < 8; n++)
                    acc[m][n] += ra[m] * rb[n];
        }
        __syncthreads();
    }

    // Epilogue
    float bv[8];
    #pragma unroll
    for (int n = 0; n < 8; n++) bv[n] = bias ? bias[bn + tx * 8 + n] : 0.f;

    #pragma unroll
    for (int m = 0; m < 8; m++) {
        int row = bm + ty * 8 + m;
        #pragma unroll
        for (int n = 0; n < 8; n += 4) {
            int col = bn + tx * 8 + n;
            float4 v;
            v.x = acc[m][n + 0] + bv[n + 0];
            v.y = acc[m][n + 1] + bv[n + 1];
            v.z = acc[m][n + 2] + bv[n + 2];
            v.w = acc[m][n + 3] + bv[n + 3];
            *(float4*)(C + (size_t)row * N + col) = v;
        }
    }
}

// ---------------------------------------------------------------------------
// Causal flash attention, fp32. 1 thread = 1 query row.
// All lanes read identical Ks/Vs addresses -> smem broadcast -> FMA-bound.
// grid: (SEQ/BQ, batch*NH), block: 128
// ---------------------------------------------------------------------------
__global__ void __launch_bounds__(128) attn_kernel(
    const float* __restrict__ qkv, float* __restrict__ ctx)
{
    const int BQ = 128, BKT = 64;
    int bh = blockIdx.y;
    int b  = bh >> 4;
    int h  = bh & 15;
    int qg = blockIdx.x * BQ + threadIdx.x;   // query index within sequence

    __shared__ float Ks[BKT][HD];
    __shared__ float Vs[BKT][HD];

    float q[HD], acc[HD];
    const float* qrow = qkv + ((size_t)(b * SEQ + qg)) * 3072 + h * HD;
    #pragma unroll
    for (int d = 0; d < HD; d += 4) {
        float4 v = *(const float4*)(qrow + d);
        q[d + 0] = v.x * 0.125f;   // fold 1/sqrt(64)
        q[d + 1] = v.y * 0.125f;
        q[d + 2] = v.z * 0.125f;
        q[d + 3] = v.w * 0.125f;
        acc[d] = acc[d + 1] = acc[d + 2] = acc[d + 3] = 0.f;
    }

    float m = -1e30f, l = 0.f;

    int ntiles = (blockIdx.x * BQ + BQ) / BKT;   // causal: keys < (qtile+1)*BQ
    for (int kt = 0; kt < ntiles; kt++) {
        int ks = kt * BKT;
        __syncthreads();
        // Cooperative K/V tile load: 64 rows x 16 float4 each
        for (int i = threadIdx.x; i < BKT * (HD / 4); i += 128) {
            int j  = i >> 4;
            int d4 = i & 15;
            const float* kr = qkv + ((size_t)(b * SEQ + ks + j)) * 3072 + 1024 + h * HD;
            ((float4*)&Ks[j][0])[d4] = ((const float4*)kr)[d4];
            ((float4*)&Vs[j][0])[d4] = ((const float4*)(kr + 1024))[d4];
        }
        __syncthreads();

        if (ks > qg) continue;   // fully-masked tile for this row

        #pragma unroll 1
        for (int g = 0; g < BKT; g += 16) {
            if (ks + g > qg) break;   // remaining groups fully masked
            float s[16];
            float mloc = m;
            #pragma unroll
            for (int jj = 0; jj < 16; jj++) {
                int j = g + jj;
                float sum = 0.f;
                #pragma unroll
                for (int d = 0; d < HD; d += 4) {
                    float4 k4 = *(const float4*)&Ks[j][d];
                    sum += q[d + 0] * k4.x;
                    sum += q[d + 1] * k4.y;
                    sum += q[d + 2] * k4.z;
                    sum += q[d + 3] * k4.w;
                }
                s[jj] = (ks + j <= qg) ? sum : -1e30f;
                mloc = fmaxf(mloc, s[jj]);
            }
            float fac = __expf(m - mloc);
            m = mloc;
            l *= fac;
            #pragma unroll
            for (int d = 0; d < HD; d++) acc[d] *= fac;
            #pragma unroll
            for (int jj = 0; jj < 16; jj++) {
                float p = __expf(s[jj] - m);
                l += p;
                #pragma unroll
                for (int d = 0; d < HD; d += 4) {
                    float4 v4 = *(const float4*)&Vs[g + jj][d];
                    acc[d + 0] += p * v4.x;
                    acc[d + 1] += p * v4.y;
                    acc[d + 2] += p * v4.z;
                    acc[d + 3] += p * v4.w;
                }
            }
        }
    }

    float inv = 1.f / l;
    float* orow = ctx + ((size_t)(b * SEQ + qg)) * NOUT + h * HD;
    #pragma unroll
    for (int d = 0; d < HD; d += 4) {
        float4 v;
        v.x = acc[d + 0] * inv;
        v.y = acc[d + 1] * inv;
        v.z = acc[d + 2] * inv;
        v.w = acc[d + 3] * inv;
        *(float4*)(orow + d) = v;
    }
}

// ---------------------------------------------------------------------------
extern "C" void kernel_launch(void* const* d_in, const int* in_sizes, int n_in,
                              void* d_out, int out_size)
{
    const float* y    = (const float*)d_in[0];
    const float* Wqkv = (const float*)d_in[1];
    const float* Wff  = (const float*)d_in[2];
    const float* bff  = (const float*)d_in[3];
    float* out = (float*)d_out;

    int M = in_sizes[0] / NIN;        // b*n = 4096
    int batch = M / SEQ;              // 2

    float *qkv_p, *ctx_p;
    cudaGetSymbolAddress((void**)&qkv_p, g_qkv);
    cudaGetSymbolAddress((void**)&ctx_p, g_ctx);

    // 1) qkv = y @ Wqkv
    {
        dim3 grid(3 * NOUT / 128, M / 128);
        sgemm128<<<grid, 256>>>(y, Wqkv, nullptr, qkv_p, M, 3 * NOUT, NIN);
    }
    // 2) causal multi-head attention
    {
        dim3 grid(SEQ / 128, batch * NH);
        attn_kernel<<<grid, 128>>>(qkv_p, ctx_p);
    }
    // 3) out = ctx @ Wff + bff
    {
        dim3 grid(NOUT / 128, M / 128);
        sgemm128<<<grid, 256>>>(ctx_p, Wff, bff, out, M, NOUT, NOUT);
    }
}

// round 3
// speedup vs baseline: 1.3820x; 1.3820x over previous
#include <cuda_runtime.h>
#include <cuda_bf16.h>
#include <cstddef>
#include <cstdint>

// Problem constants (fixed-shape bench)
// y:    [2, 2048, 1024] fp32
// Wqkv: [1024, 3072]    fp32
// Wff:  [1024, 1024]    fp32
// bff:  [1024]          fp32
// out:  [2, 2048, 1024] fp32

#define SEQ 2048
#define NIN 1024
#define NOUT 1024
#define NH 16
#define HD 64
#define MTOT 4096   // b*n

// ---------------------------------------------------------------------------
// Device scratch (allocation-free per harness rules)
// ---------------------------------------------------------------------------
__device__ float g_qkv[MTOT * 3 * 1024];            // fp32 qkv
__device__ float g_ctx[MTOT * 1024];                // fp32 attention output
__device__ __nv_bfloat16 g_Ahi[MTOT * 1024];        // split A operand (y, then ctx)
__device__ __nv_bfloat16 g_Alo[MTOT * 1024];
__device__ __nv_bfloat16 g_Bhi[3072 * 1024];        // split, transposed W
__device__ __nv_bfloat16 g_Blo[3072 * 1024];

// ---------------------------------------------------------------------------
// PTX wrappers (all sm_80+ features: compile clean at compute_103)
// ---------------------------------------------------------------------------
__device__ __forceinline__ uint32_t smem_u32(const void* p) {
    uint32_t a;
    asm("{ .reg .u64 t; cvta.to.shared.u64 t, %1; cvt.u32.u64 %0, t; }" : "=r"(a) : "l"(p));
    return a;
}

#define CP_ASYNC16(dst, src) \
    asm volatile("cp.async.cg.shared.global [%0], [%1], 16;" :: "r"(dst), "l"(src))
#define CP_COMMIT() asm volatile("cp.async.commit_group;" ::: "memory")
#define CP_WAIT1()  asm volatile("cp.async.wait_group 1;" ::: "memory")
#define CP_WAIT0()  asm volatile("cp.async.wait_group 0;" ::: "memory")

__device__ __forceinline__ void ldsm4(uint32_t& r0, uint32_t& r1, uint32_t& r2,
                                      uint32_t& r3, uint32_t addr) {
    asm volatile("ldmatrix.sync.aligned.m8n8.x4.shared.b16 {%0,%1,%2,%3}, [%4];"
                 : "=r"(r0), "=r"(r1), "=r"(r2), "=r"(r3) : "r"(addr));
}

__device__ __forceinline__ void mma_bf16(float* c, const uint32_t* a, const uint32_t* b) {
    asm volatile(
        "mma.sync.aligned.m16n8k16.row.col.f32.bf16.bf16.f32 "
        "{%0,%1,%2,%3}, {%4,%5,%6,%7}, {%8,%9}, {%0,%1,%2,%3};"
        : "+f"(c[0]), "+f"(c[1]), "+f"(c[2]), "+f"(c[3])
        : "r"(a[0]), "r"(a[1]), "r"(a[2]), "r"(a[3]), "r"(b[0]), "r"(b[1]));
}

// ---------------------------------------------------------------------------
// Split conversion: fp32 -> (hi, lo) bf16, elementwise. n4 = elems/4.
// ---------------------------------------------------------------------------
__global__ void __launch_bounds__(256) sconv(const float* __restrict__ in,
                                             __nv_bfloat16* __restrict__ hi,
                                             __nv_bfloat16* __restrict__ lo, int n4)
{
    int i = blockIdx.x * 256 + threadIdx.x;
    if (i >= n4) return;
    float4 v = ((const float4*)in)[i];
    __nv_bfloat16 h0 = __float2bfloat16(v.x), h1 = __float2bfloat16(v.y);
    __nv_bfloat16 h2 = __float2bfloat16(v.z), h3 = __float2bfloat16(v.w);
    __nv_bfloat16 l0 = __float2bfloat16(v.x - __bfloat162float(h0));
    __nv_bfloat16 l1 = __float2bfloat16(v.y - __bfloat162float(h1));
    __nv_bfloat16 l2 = __float2bfloat16(v.z - __bfloat162float(h2));
    __nv_bfloat16 l3 = __float2bfloat16(v.w - __bfloat162float(h3));
    ((__nv_bfloat162*)hi)[2 * i + 0] = __nv_bfloat162(h0, h1);
    ((__nv_bfloat162*)hi)[2 * i + 1] = __nv_bfloat162(h2, h3);
    ((__nv_bfloat162*)lo)[2 * i + 0] = __nv_bfloat162(l0, l1);
    ((__nv_bfloat162*)lo)[2 * i + 1] = __nv_bfloat162(l2, l3);
}

// ---------------------------------------------------------------------------
// Transpose + split: W[K,N] fp32 -> Thi/Tlo[N,K] bf16
// ---------------------------------------------------------------------------
__global__ void __launch_bounds__(256) tconv(const float* __restrict__ W,
                                             __nv_bfloat16* __restrict__ Thi,
                                             __nv_bfloat16* __restrict__ Tlo,
                                             int K, int N)
{
    __shared__ float tile[32][33];
    int bx = blockIdx.x * 32;   // N offset
    int by = blockIdx.y * 32;   // K offset
    int tx = threadIdx.x & 31;
    int ty = threadIdx.x >> 5;  // 0..7
    #pragma unroll
    for (int r = 0; r < 4; r++)
        tile[ty + r * 8][tx] = W[(size_t)(by + ty + r * 8) * N + bx + tx];
    __syncthreads();
    #pragma unroll
    for (int r = 0; r < 4; r++) {
        float x = tile[tx][ty + r * 8];
        __nv_bfloat16 h = __float2bfloat16(x);
        __nv_bfloat16 l = __float2bfloat16(x - __bfloat162float(h));
        size_t o = (size_t)(bx + ty + r * 8) * K + by + tx;
        Thi[o] = h;
        Tlo[o] = l;
    }
}

// ---------------------------------------------------------------------------
// HMMA GEMM: C[M,N] = A[M,K] @ Bt[N,K]^T (+bias), split-bf16 3-product.
// 128x128 CTA tile, 8 warps (64x32 warp tile), BK=32, cp.async double buffer.
// smem rows: 32 bf16 padded to 40 (80B stride -> conflict-free ldmatrix).
// ---------------------------------------------------------------------------
#define HG_TILE  10240                 // bytes per operand tile (128 * 80)
#define HG_BUF   (4 * HG_TILE)         // AHI ALO BHI BLO
#define HG_SMEM  (2 * HG_BUF)          // double buffered = 81920

__global__ void __launch_bounds__(256) hgemm128(
    const __nv_bfloat16* __restrict__ Ahi, const __nv_bfloat16* __restrict__ Alo,
    const __nv_bfloat16* __restrict__ Bhi, const __nv_bfloat16* __restrict__ Blo,
    const float* __restrict__ bias, float* __restrict__ C, int N, int K)
{
    extern __shared__ char sm[];
    uint32_t smb = smem_u32(sm);
    int tid  = threadIdx.x;
    int lane = tid & 31;
    int w    = tid >> 5;       // 0..7
    int wm   = w >> 2;         // 0..1  (64-row band)
    int wn   = w & 3;          // 0..3  (32-col band)

    int bm = blockIdx.y * 128;
    int bn = blockIdx.x * 128;
    int nch = K / 32;

    float acc[4][4][4];
    #pragma unroll
    for (int mf = 0; mf < 4; mf++)
        #pragma unroll
        for (int nf = 0; nf < 4; nf++)
            #pragma unroll
            for (int j = 0; j < 4; j++) acc[mf][nf][j] = 0.f;

    // ---- cp.async tile loader -------------------------------------------
    auto load_chunk = [&](int kc, int buf) {
        uint32_t base = smb + buf * HG_BUF;
        #pragma unroll
        for (int i = 0; i < 2; i++) {
            int u   = tid + i * 256;       // 0..511
            int row = u >> 2;              // 0..127
            int c   = u & 3;               // 16B chunk within 64B row
            uint32_t so = (uint32_t)(row * 80 + c * 16);
            size_t ga = (size_t)(bm + row) * K + kc * 32 + c * 8;
            size_t gb = (size_t)(bn + row) * K + kc * 32 + c * 8;
            CP_ASYNC16(base + 0 * HG_TILE + so, Ahi + ga);
            CP_ASYNC16(base + 1 * HG_TILE + so, Alo + ga);
            CP_ASYNC16(base + 2 * HG_TILE + so, Bhi + gb);
            CP_ASYNC16(base + 3 * HG_TILE + so, Blo + gb);
        }
    };

    load_chunk(0, 0);
    CP_COMMIT();

    for (int kc = 0; kc < nch; kc++) {
        int buf = kc & 1;
        if (kc + 1 < nch) {
            load_chunk(kc + 1, buf ^ 1);
            CP_COMMIT();
            CP_WAIT1();
        } else {
            CP_WAIT0();
        }
        __syncthreads();

        uint32_t sA  = smb + buf * HG_BUF;
        uint32_t sAl = sA + HG_TILE;
        uint32_t sB  = sA + 2 * HG_TILE;
        uint32_t sBl = sA + 3 * HG_TILE;

        #pragma unroll
        for (int ks = 0; ks < 2; ks++) {
            uint32_t ah[4][4], al[4][4], bh[4][2], bl[4][2];

            // A fragments: 16x16 tiles, ldmatrix.x4
            int arow = wm * 64 + (lane & 15);
            int acol = ks * 16 + (lane >> 4) * 8;
            #pragma unroll
            for (int mf = 0; mf < 4; mf++) {
                uint32_t off = (uint32_t)((arow + mf * 16) * 80 + acol * 2);
                ldsm4(ah[mf][0], ah[mf][1], ah[mf][2], ah[mf][3], sA + off);
                ldsm4(al[mf][0], al[mf][1], al[mf][2], al[mf][3], sAl + off);
            }
            // B fragments: x4 covers two n8 frags
            int brow = wn * 32 + (lane & 7) + ((lane >> 4) & 1) * 8;
            int bcol = ks * 16 + ((lane >> 3) & 1) * 8;
            #pragma unroll
            for (int ng = 0; ng < 2; ng++) {
                uint32_t off = (uint32_t)((brow + ng * 16) * 80 + bcol * 2);
                ldsm4(bh[2 * ng][0], bh[2 * ng][1], bh[2 * ng + 1][0], bh[2 * ng + 1][1], sB + off);
                ldsm4(bl[2 * ng][0], bl[2 * ng][1], bl[2 * ng + 1][0], bl[2 * ng + 1][1], sBl + off);
            }

            #pragma unroll
            for (int mf = 0; mf < 4; mf++)
                #pragma unroll
                for (int nf = 0; nf < 4; nf++)
                    mma_bf16(acc[mf][nf], ah[mf], bh[nf]);
            #pragma unroll
            for (int mf = 0; mf < 4; mf++)
                #pragma unroll
                for (int nf = 0; nf < 4; nf++)
                    mma_bf16(acc[mf][nf], ah[mf], bl[nf]);
            #pragma unroll
            for (int mf = 0; mf < 4; mf++)
                #pragma unroll
                for (int nf = 0; nf < 4; nf++)
                    mma_bf16(acc[mf][nf], al[mf], bh[nf]);
        }
        __syncthreads();
    }

    // ---- epilogue --------------------------------------------------------
    int r0 = bm + wm * 64 + (lane >> 2);
    int c0 = bn + wn * 32 + 2 * (lane & 3);
    #pragma unroll
    for (int mf = 0; mf < 4; mf++) {
        #pragma unroll
        for (int nf = 0; nf < 4; nf++) {
            int row = r0 + mf * 16;
            int col = c0 + nf * 8;
            float b0 = bias ? bias[col] : 0.f;
            float b1 = bias ? bias[col + 1] : 0.f;
            float2 v0 = make_float2(acc[mf][nf][0] + b0, acc[mf][nf][1] + b1);
            float2 v1 = make_float2(acc[mf][nf][2] + b0, acc[mf][nf][3] + b1);
            *(float2*)(C + (size_t)row * N + col)       = v0;
            *(float2*)(C + (size_t)(row + 8) * N + col) = v1;
        }
    }
}

// ---------------------------------------------------------------------------
// Causal flash attention, fp32. 1 thread = 1 query row.
// ---------------------------------------------------------------------------
__global__ void __launch_bounds__(128) attn_kernel(
    const float* __restrict__ qkv, float* __restrict__ ctx)
{
    const int BQ = 128, BKT = 64;
    int bh = blockIdx.y;
    int b  = bh >> 4;
    int h  = bh & 15;
    int qtile = gridDim.x - 1 - blockIdx.x;   // longest first
    int qg = qtile * BQ + threadIdx.x;

    __shared__ float Ks[BKT][HD];
    __shared__ float Vs[BKT][HD];

    float q[HD], acc[HD];
    const float* qrow = qkv + ((size_t)(b * SEQ + qg)) * 3072 + h * HD;
    #pragma unroll
    for (int d = 0; d < HD; d += 4) {
        float4 v = *(const float4*)(qrow + d);
        q[d + 0] = v.x * 0.125f;
        q[d + 1] = v.y * 0.125f;
        q[d + 2] = v.z * 0.125f;
        q[d + 3] = v.w * 0.125f;
        acc[d] = acc[d + 1] = acc[d + 2] = acc[d + 3] = 0.f;
    }

    float m = -1e30f, l = 0.f;

    int ntiles = (qtile * BQ + BQ) / BKT;
    for (int kt = 0; kt < ntiles; kt++) {
        int ks = kt * BKT;
        __syncthreads();
        for (int i = threadIdx.x; i < BKT * (HD / 4); i += 128) {
            int j  = i >> 4;
            int d4 = i & 15;
            const float* kr = qkv + ((size_t)(b * SEQ + ks + j)) * 3072 + 1024 + h * HD;
            ((float4*)&Ks[j][0])[d4] = ((const float4*)kr)[d4];
            ((float4*)&Vs[j][0])[d4] = ((const float4*)(kr + 1024))[d4];
        }
        __syncthreads();

        if (ks > qg) continue;

        #pragma unroll 1
        for (int g = 0; g < BKT; g += 16) {
            if (ks + g > qg) break;
            float s[16];
            float mloc = m;
            #pragma unroll
            for (int jj = 0; jj < 16; jj++) {
                int j = g + jj;
                float sum = 0.f;
                #pragma unroll
                for (int d = 0; d < HD; d += 4) {
                    float4 k4 = *(const float4*)&Ks[j][d];
                    sum += q[d + 0] * k4.x;
                    sum += q[d + 1] * k4.y;
                    sum += q[d + 2] * k4.z;
                    sum += q[d + 3] * k4.w;
                }
                s[jj] = (ks + j <= qg) ? sum : -1e30f;
                mloc = fmaxf(mloc, s[jj]);
            }
            float fac = __expf(m - mloc);
            m = mloc;
            l *= fac;
            #pragma unroll
            for (int d = 0; d < HD; d++) acc[d] *= fac;
            #pragma unroll
            for (int jj = 0; jj < 16; jj++) {
                float p = __expf(s[jj] - m);
                l += p;
                #pragma unroll
                for (int d = 0; d < HD; d += 4) {
                    float4 v4 = *(const float4*)&Vs[g + jj][d];
                    acc[d + 0] += p * v4.x;
                    acc[d + 1] += p * v4.y;
                    acc[d + 2] += p * v4.z;
                    acc[d + 3] += p * v4.w;
                }
            }
        }
    }

    float inv = 1.f / l;
    float* orow = ctx + ((size_t)(b * SEQ + qg)) * NOUT + h * HD;
    #pragma unroll
    for (int d = 0; d < HD; d += 4) {
        float4 v;
        v.x = acc[d + 0] * inv;
        v.y = acc[d + 1] * inv;
        v.z = acc[d + 2] * inv;
        v.w = acc[d + 3] * inv;
        *(float4*)(orow + d) = v;
    }
}

// ---------------------------------------------------------------------------
extern "C" void kernel_launch(void* const* d_in, const int* in_sizes, int n_in,
                              void* d_out, int out_size)
{
    const float* y    = (const float*)d_in[0];
    const float* Wqkv = (const float*)d_in[1];
    const float* Wff  = (const float*)d_in[2];
    const float* bff  = (const float*)d_in[3];
    float* out = (float*)d_out;

    float *qkv_p, *ctx_p;
    __nv_bfloat16 *ahi, *alo, *bhi, *blo;
    cudaGetSymbolAddress((void**)&qkv_p, g_qkv);
    cudaGetSymbolAddress((void**)&ctx_p, g_ctx);
    cudaGetSymbolAddress((void**)&ahi, g_Ahi);
    cudaGetSymbolAddress((void**)&alo, g_Alo);
    cudaGetSymbolAddress((void**)&bhi, g_Bhi);
    cudaGetSymbolAddress((void**)&blo, g_Blo);

    cudaFuncSetAttribute(hgemm128, cudaFuncAttributeMaxDynamicSharedMemorySize, HG_SMEM);

    // 1) split/transpose weights + activations
    tconv<<<dim3(3072 / 32, 1024 / 32), 256>>>(Wqkv, bhi, blo, 1024, 3072);
    sconv<<<(MTOT * 1024 / 4 + 255) / 256, 256>>>(y, ahi, alo, MTOT * 1024 / 4);

    // 2) qkv = y @ Wqkv   (HMMA, split-bf16)
    hgemm128<<<dim3(3072 / 128, MTOT / 128), 256, HG_SMEM>>>(
        ahi, alo, bhi, blo, nullptr, qkv_p, 3072, 1024);

    // 3) causal multi-head attention (fp32)
    attn_kernel<<<dim3(SEQ / 128, 2 * NH), 128>>>(qkv_p, ctx_p);

    // 4) out = ctx @ Wff + bff  (HMMA, split-bf16)
    sconv<<<(MTOT * 1024 / 4 + 255) / 256, 256>>>(ctx_p, ahi, alo, MTOT * 1024 / 4);
    tconv<<<dim3(1024 / 32, 1024 / 32), 256>>>(Wff, bhi, blo, 1024, 1024);
    hgemm128<<<dim3(1024 / 128, MTOT / 128), 256, HG_SMEM>>>(
        ahi, alo, bhi, blo, bff, out, 1024, 1024);
}

// round 4
// speedup vs baseline: 3.6148x; 2.6156x over previous
#include <cuda_runtime.h>
#include <cuda_bf16.h>
#include <cstddef>
#include <cstdint>

// Problem constants (fixed-shape bench)
// y: [2,2048,1024] f32; Wqkv: [1024,3072] f32; Wff: [1024,1024] f32; bff:[1024]
// out: [2,2048,1024] f32

#define SEQ 2048
#define NH 16
#define HD 64
#define MTOT 4096   // b*n

// ---------------------------------------------------------------------------
// Device scratch (allocation-free per harness rules)
// ---------------------------------------------------------------------------
__device__ __nv_bfloat16 g_Ahi[MTOT * 1024];        // split A (y for GEMM1, ctx for GEMM2)
__device__ __nv_bfloat16 g_Alo[MTOT * 1024];
__device__ __nv_bfloat16 g_Bhi[3072 * 1024];        // split transposed W
__device__ __nv_bfloat16 g_Blo[3072 * 1024];
// attention operands, head-major [b*16+h][n][64], Q pre-scaled by 0.125
__device__ __nv_bfloat16 g_Qhi[32 * SEQ * HD];
__device__ __nv_bfloat16 g_Qlo[32 * SEQ * HD];
__device__ __nv_bfloat16 g_Khi[32 * SEQ * HD];
__device__ __nv_bfloat16 g_Klo[32 * SEQ * HD];
__device__ __nv_bfloat16 g_Vhi[32 * SEQ * HD];
__device__ __nv_bfloat16 g_Vlo[32 * SEQ * HD];

// ---------------------------------------------------------------------------
// PTX wrappers (sm_80+, compile clean at compute_103)
// ---------------------------------------------------------------------------
__device__ __forceinline__ uint32_t smem_u32(const void* p) {
    uint32_t a;
    asm("{ .reg .u64 t; cvta.to.shared.u64 t, %1; cvt.u32.u64 %0, t; }" : "=r"(a) : "l"(p));
    return a;
}
#define CP_ASYNC16(dst, src) \
    asm volatile("cp.async.cg.shared.global [%0], [%1], 16;" :: "r"(dst), "l"(src))
#define CP_COMMIT() asm volatile("cp.async.commit_group;" ::: "memory")
#define CP_WAIT1()  asm volatile("cp.async.wait_group 1;" ::: "memory")
#define CP_WAIT0()  asm volatile("cp.async.wait_group 0;" ::: "memory")

__device__ __forceinline__ void ldsm4(uint32_t& r0, uint32_t& r1, uint32_t& r2,
                                      uint32_t& r3, uint32_t addr) {
    asm volatile("ldmatrix.sync.aligned.m8n8.x4.shared.b16 {%0,%1,%2,%3}, [%4];"
                 : "=r"(r0), "=r"(r1), "=r"(r2), "=r"(r3) : "r"(addr));
}
__device__ __forceinline__ void ldsm4t(uint32_t& r0, uint32_t& r1, uint32_t& r2,
                                       uint32_t& r3, uint32_t addr) {
    asm volatile("ldmatrix.sync.aligned.m8n8.x4.trans.shared.b16 {%0,%1,%2,%3}, [%4];"
                 : "=r"(r0), "=r"(r1), "=r"(r2), "=r"(r3) : "r"(addr));
}
__device__ __forceinline__ void mma_bf16(float* c, const uint32_t* a, const uint32_t* b) {
    asm volatile(
        "mma.sync.aligned.m16n8k16.row.col.f32.bf16.bf16.f32 "
        "{%0,%1,%2,%3}, {%4,%5,%6,%7}, {%8,%9}, {%0,%1,%2,%3};"
        : "+f"(c[0]), "+f"(c[1]), "+f"(c[2]), "+f"(c[3])
        : "r"(a[0]), "r"(a[1]), "r"(a[2]), "r"(a[3]), "r"(b[0]), "r"(b[1]));
}
__device__ __forceinline__ uint32_t packbf2(__nv_bfloat16 a, __nv_bfloat16 b) {
    __nv_bfloat162 v(a, b);
    return *reinterpret_cast<uint32_t*>(&v);
}

// ---------------------------------------------------------------------------
// Split conversion: fp32 -> (hi, lo) bf16, elementwise. n4 = elems/4.
// ---------------------------------------------------------------------------
__global__ void __launch_bounds__(256) sconv(const float* __restrict__ in,
                                             __nv_bfloat16* __restrict__ hi,
                                             __nv_bfloat16* __restrict__ lo, int n4)
{
    int i = blockIdx.x * 256 + threadIdx.x;
    if (i >= n4) return;
    float4 v = ((const float4*)in)[i];
    __nv_bfloat16 h0 = __float2bfloat16(v.x), h1 = __float2bfloat16(v.y);
    __nv_bfloat16 h2 = __float2bfloat16(v.z), h3 = __float2bfloat16(v.w);
    __nv_bfloat16 l0 = __float2bfloat16(v.x - __bfloat162float(h0));
    __nv_bfloat16 l1 = __float2bfloat16(v.y - __bfloat162float(h1));
    __nv_bfloat16 l2 = __float2bfloat16(v.z - __bfloat162float(h2));
    __nv_bfloat16 l3 = __float2bfloat16(v.w - __bfloat162float(h3));
    ((__nv_bfloat162*)hi)[2 * i + 0] = __nv_bfloat162(h0, h1);
    ((__nv_bfloat162*)hi)[2 * i + 1] = __nv_bfloat162(h2, h3);
    ((__nv_bfloat162*)lo)[2 * i + 0] = __nv_bfloat162(l0, l1);
    ((__nv_bfloat162*)lo)[2 * i + 1] = __nv_bfloat162(l2, l3);
}

// ---------------------------------------------------------------------------
// Transpose + split: W[K,N] fp32 -> Thi/Tlo[N,K] bf16
// ---------------------------------------------------------------------------
__global__ void __launch_bounds__(256) tconv(const float* __restrict__ W,
                                             __nv_bfloat16* __restrict__ Thi,
                                             __nv_bfloat16* __restrict__ Tlo,
                                             int K, int N)
{
    __shared__ float tile[32][33];
    int bx = blockIdx.x * 32;
    int by = blockIdx.y * 32;
    int tx = threadIdx.x & 31;
    int ty = threadIdx.x >> 5;
    #pragma unroll
    for (int r = 0; r < 4; r++)
        tile[ty + r * 8][tx] = W[(size_t)(by + ty + r * 8) * N + bx + tx];
    __syncthreads();
    #pragma unroll
    for (int r = 0; r < 4; r++) {
        float x = tile[tx][ty + r * 8];
        __nv_bfloat16 h = __float2bfloat16(x);
        __nv_bfloat16 l = __float2bfloat16(x - __bfloat162float(h));
        size_t o = (size_t)(bx + ty + r * 8) * K + by + tx;
        Thi[o] = h;
        Tlo[o] = l;
    }
}

// ---------------------------------------------------------------------------
// HMMA GEMM: C[M,N] = A[M,K] @ Bt[N,K]^T, split-bf16 3-product.
// mode 0: C fp32 (+bias). mode 1: split-bf16 qkv output to g_Q/K/V arrays.
// ---------------------------------------------------------------------------
#define HG_TILE  10240                 // 128 * 80
#define HG_BUF   (4 * HG_TILE)
#define HG_SMEM  (2 * HG_BUF)

__global__ void __launch_bounds__(256) hgemm128(
    const __nv_bfloat16* __restrict__ Ahi, const __nv_bfloat16* __restrict__ Alo,
    const __nv_bfloat16* __restrict__ Bhi, const __nv_bfloat16* __restrict__ Blo,
    const float* __restrict__ bias, float* __restrict__ C, int N, int K, int mode)
{
    extern __shared__ char sm[];
    uint32_t smb = smem_u32(sm);
    int tid  = threadIdx.x;
    int lane = tid & 31;
    int w    = tid >> 5;
    int wm   = w >> 2;
    int wn   = w & 3;

    int bm = blockIdx.y * 128;
    int bn = blockIdx.x * 128;
    int nch = K / 32;

    float acc[4][4][4];
    #pragma unroll
    for (int mf = 0; mf < 4; mf++)
        #pragma unroll
        for (int nf = 0; nf < 4; nf++)
            #pragma unroll
            for (int j = 0; j < 4; j++) acc[mf][nf][j] = 0.f;

    auto load_chunk = [&](int kc, int buf) {
        uint32_t base = smb + buf * HG_BUF;
        #pragma unroll
        for (int i = 0; i < 2; i++) {
            int u   = tid + i * 256;
            int row = u >> 2;
            int c   = u & 3;
            uint32_t so = (uint32_t)(row * 80 + c * 16);
            size_t ga = (size_t)(bm + row) * K + kc * 32 + c * 8;
            size_t gb = (size_t)(bn + row) * K + kc * 32 + c * 8;
            CP_ASYNC16(base + 0 * HG_TILE + so, Ahi + ga);
            CP_ASYNC16(base + 1 * HG_TILE + so, Alo + ga);
            CP_ASYNC16(base + 2 * HG_TILE + so, Bhi + gb);
            CP_ASYNC16(base + 3 * HG_TILE + so, Blo + gb);
        }
    };

    load_chunk(0, 0);
    CP_COMMIT();

    for (int kc = 0; kc < nch; kc++) {
        int buf = kc & 1;
        if (kc + 1 < nch) {
            load_chunk(kc + 1, buf ^ 1);
            CP_COMMIT();
            CP_WAIT1();
        } else {
            CP_WAIT0();
        }
        __syncthreads();

        uint32_t sA  = smb + buf * HG_BUF;
        uint32_t sAl = sA + HG_TILE;
        uint32_t sB  = sA + 2 * HG_TILE;
        uint32_t sBl = sA + 3 * HG_TILE;

        #pragma unroll
        for (int ks = 0; ks < 2; ks++) {
            uint32_t ah[4][4], al[4][4], bh[4][2], bl[4][2];
            int arow = wm * 64 + (lane & 15);
            int acol = ks * 16 + (lane >> 4) * 8;
            #pragma unroll
            for (int mf = 0; mf < 4; mf++) {
                uint32_t off = (uint32_t)((arow + mf * 16) * 80 + acol * 2);
                ldsm4(ah[mf][0], ah[mf][1], ah[mf][2], ah[mf][3], sA + off);
                ldsm4(al[mf][0], al[mf][1], al[mf][2], al[mf][3], sAl + off);
            }
            int brow = wn * 32 + (lane & 7) + ((lane >> 4) & 1) * 8;
            int bcol = ks * 16 + ((lane >> 3) & 1) * 8;
            #pragma unroll
            for (int ng = 0; ng < 2; ng++) {
                uint32_t off = (uint32_t)((brow + ng * 16) * 80 + bcol * 2);
                ldsm4(bh[2 * ng][0], bh[2 * ng][1], bh[2 * ng + 1][0], bh[2 * ng + 1][1], sB + off);
                ldsm4(bl[2 * ng][0], bl[2 * ng][1], bl[2 * ng + 1][0], bl[2 * ng + 1][1], sBl + off);
            }
            #pragma unroll
            for (int mf = 0; mf < 4; mf++)
                #pragma unroll
                for (int nf = 0; nf < 4; nf++)
                    mma_bf16(acc[mf][nf], ah[mf], bh[nf]);
            #pragma unroll
            for (int mf = 0; mf < 4; mf++)
                #pragma unroll
                for (int nf = 0; nf < 4; nf++)
                    mma_bf16(acc[mf][nf], ah[mf], bl[nf]);
            #pragma unroll
            for (int mf = 0; mf < 4; mf++)
                #pragma unroll
                for (int nf = 0; nf < 4; nf++)
                    mma_bf16(acc[mf][nf], al[mf], bh[nf]);
        }
        __syncthreads();
    }

    int r0 = bm + wm * 64 + (lane >> 2);
    int c0 = bn + wn * 32 + 2 * (lane & 3);

    if (mode == 0) {
        #pragma unroll
        for (int mf = 0; mf < 4; mf++) {
            #pragma unroll
            for (int nf = 0; nf < 4; nf++) {
                int row = r0 + mf * 16;
                int col = c0 + nf * 8;
                float b0 = bias ? bias[col] : 0.f;
                float b1 = bias ? bias[col + 1] : 0.f;
                float2 v0 = make_float2(acc[mf][nf][0] + b0, acc[mf][nf][1] + b1);
                float2 v1 = make_float2(acc[mf][nf][2] + b0, acc[mf][nf][3] + b1);
                *(float2*)(C + (size_t)row * N + col)       = v0;
                *(float2*)(C + (size_t)(row + 8) * N + col) = v1;
            }
        }
    } else {
        // qkv split output: col -> which/h/d, row -> b/n
        #pragma unroll
        for (int mf = 0; mf < 4; mf++) {
            #pragma unroll
            for (int nf = 0; nf < 4; nf++) {
                int col   = c0 + nf * 8;
                int which = col >> 10;
                int h     = (col >> 6) & 15;
                int d     = col & 63;
                float scale = (which == 0) ? 0.125f : 1.0f;
                __nv_bfloat16* dhi = (which == 0) ? g_Qhi : (which == 1) ? g_Khi : g_Vhi;
                __nv_bfloat16* dlo = (which == 0) ? g_Qlo : (which == 1) ? g_Klo : g_Vlo;
                #pragma unroll
                for (int half = 0; half < 2; half++) {
                    int row = r0 + mf * 16 + half * 8;
                    int b = row >> 11, n = row & 2047;
                    float v0 = acc[mf][nf][2 * half + 0] * scale;
                    float v1 = acc[mf][nf][2 * half + 1] * scale;
                    __nv_bfloat16 h0 = __float2bfloat16(v0);
                    __nv_bfloat16 h1 = __float2bfloat16(v1);
                    __nv_bfloat16 l0 = __float2bfloat16(v0 - __bfloat162float(h0));
                    __nv_bfloat16 l1 = __float2bfloat16(v1 - __bfloat162float(h1));
                    size_t dst = ((size_t)((b * 16 + h) * SEQ + n)) * HD + d;
                    *(__nv_bfloat162*)(dhi + dst) = __nv_bfloat162(h0, h1);
                    *(__nv_bfloat162*)(dlo + dst) = __nv_bfloat162(l0, l1);
                }
            }
        }
    }
}

// ---------------------------------------------------------------------------
// Tensor-core causal flash attention, split-bf16 3-product for QK^T and PV.
// CTA: 128 q-rows of one (b,h); 8 warps x 16 rows. K/V tiles of 64 keys,
// cp.async double-buffered. smem rows padded to 144B (conflict-free ldmatrix).
// ---------------------------------------------------------------------------
#define ATT_STRIDE 144
#define ATT_QTILE  (128 * ATT_STRIDE)          // 18432
#define ATT_KTILE  (64 * ATT_STRIDE)           // 9216
#define ATT_KV0    (2 * ATT_QTILE)             // 36864
#define ATT_KVBUF  (4 * ATT_KTILE)             // 36864
#define ATT_SMEM   (ATT_KV0 + 2 * ATT_KVBUF)   // 110592

__global__ void __launch_bounds__(256) attn_mma()
{
    extern __shared__ char sm[];
    uint32_t smb = smem_u32(sm);
    int tid  = threadIdx.x;
    int lane = tid & 31;
    int w    = tid >> 5;

    int qt = (int)gridDim.x - 1 - (int)blockIdx.x;   // longest first
    int bh = blockIdx.y;
    size_t base = (size_t)bh * (SEQ * HD);

    // ---- Q tile loads (group 0) ----
    #pragma unroll
    for (int i = 0; i < 8; i++) {
        int u    = tid + i * 256;        // 0..2047
        int tens = u >> 10;              // 0:hi 1:lo
        int row  = (u >> 3) & 127;
        int c    = u & 7;
        const __nv_bfloat16* src = (tens ? g_Qlo : g_Qhi) + base
                                 + (size_t)(128 * qt + row) * HD + c * 8;
        CP_ASYNC16(smb + tens * ATT_QTILE + row * ATT_STRIDE + c * 16, src);
    }
    CP_COMMIT();

    auto load_kv = [&](int kt, int buf) {
        uint32_t bb = smb + ATT_KV0 + buf * ATT_KVBUF;
        #pragma unroll
        for (int i = 0; i < 8; i++) {
            int u    = tid + i * 256;    // 0..2047
            int tens = u >> 9;           // 0:Khi 1:Klo 2:Vhi 3:Vlo
            int row  = (u >> 3) & 63;
            int c    = u & 7;
            const __nv_bfloat16* src =
                (tens == 0 ? g_Khi : tens == 1 ? g_Klo : tens == 2 ? g_Vhi : g_Vlo)
                + base + (size_t)(64 * kt + row) * HD + c * 8;
            CP_ASYNC16(bb + tens * ATT_KTILE + row * ATT_STRIDE + c * 16, src);
        }
    };

    int ktmax = 2 * qt + 1;
    load_kv(0, 0);
    CP_COMMIT();

    float O[8][4];
    #pragma unroll
    for (int nf = 0; nf < 8; nf++)
        #pragma unroll
        for (int j = 0; j < 4; j++) O[nf][j] = 0.f;
    float m0 = -1e30f, m1 = -1e30f, l0 = 0.f, l1 = 0.f;
    uint32_t qh[4][4], ql[4][4];

    for (int kt = 0; kt <= ktmax; kt++) {
        int buf = kt & 1;
        if (kt < ktmax) {
            load_kv(kt + 1, buf ^ 1);
            CP_COMMIT();
            CP_WAIT1();
        } else {
            CP_WAIT0();
        }
        __syncthreads();

        if (kt == 0) {
            // resident Q fragments
            int arow = w * 16 + (lane & 15);
            #pragma unroll
            for (int ks = 0; ks < 4; ks++) {
                uint32_t off = (uint32_t)(arow * ATT_STRIDE + (ks * 16 + (lane >> 4) * 8) * 2);
                ldsm4(qh[ks][0], qh[ks][1], qh[ks][2], qh[ks][3], smb + off);
                ldsm4(ql[ks][0], ql[ks][1], ql[ks][2], ql[ks][3], smb + ATT_QTILE + off);
            }
        }

        uint32_t sK  = smb + ATT_KV0 + buf * ATT_KVBUF;
        uint32_t sKl = sK + ATT_KTILE;
        uint32_t sV  = sK + 2 * ATT_KTILE;
        uint32_t sVl = sK + 3 * ATT_KTILE;

        // ---- S = Q K^T ----
        float s[8][4];
        #pragma unroll
        for (int nf = 0; nf < 8; nf++)
            #pragma unroll
            for (int j = 0; j < 4; j++) s[nf][j] = 0.f;

        #pragma unroll
        for (int ks = 0; ks < 4; ks++) {
            uint32_t kh[8][2], kl[8][2];
            int kcol = (ks * 16 + ((lane >> 3) & 1) * 8) * 2;
            #pragma unroll
            for (int ng = 0; ng < 4; ng++) {
                int krow = ng * 16 + (lane & 7) + (lane >> 4) * 8;
                uint32_t off = (uint32_t)(krow * ATT_STRIDE + kcol);
                ldsm4(kh[2 * ng][0], kh[2 * ng][1], kh[2 * ng + 1][0], kh[2 * ng + 1][1], sK + off);
                ldsm4(kl[2 * ng][0], kl[2 * ng][1], kl[2 * ng + 1][0], kl[2 * ng + 1][1], sKl + off);
            }
            #pragma unroll
            for (int nf = 0; nf < 8; nf++) mma_bf16(s[nf], qh[ks], kh[nf]);
            #pragma unroll
            for (int nf = 0; nf < 8; nf++) mma_bf16(s[nf], qh[ks], kl[nf]);
            #pragma unroll
            for (int nf = 0; nf < 8; nf++) mma_bf16(s[nf], ql[ks], kh[nf]);
        }

        // ---- causal mask (diagonal tiles only) ----
        int row0 = 128 * qt + w * 16 + (lane >> 2);
        if (kt >= 2 * qt) {
            int cb = 64 * kt + 2 * (lane & 3);
            #pragma unroll
            for (int nf = 0; nf < 8; nf++) {
                int c = cb + nf * 8;
                if (c     > row0)     s[nf][0] = -1e30f;
                if (c + 1 > row0)     s[nf][1] = -1e30f;
                if (c     > row0 + 8) s[nf][2] = -1e30f;
                if (c + 1 > row0 + 8) s[nf][3] = -1e30f;
            }
        }

        // ---- online softmax ----
        float mx0 = m0, mx1 = m1;
        #pragma unroll
        for (int nf = 0; nf < 8; nf++) {
            mx0 = fmaxf(mx0, fmaxf(s[nf][0], s[nf][1]));
            mx1 = fmaxf(mx1, fmaxf(s[nf][2], s[nf][3]));
        }
        mx0 = fmaxf(mx0, __shfl_xor_sync(0xFFFFFFFF, mx0, 1));
        mx0 = fmaxf(mx0, __shfl_xor_sync(0xFFFFFFFF, mx0, 2));
        mx1 = fmaxf(mx1, __shfl_xor_sync(0xFFFFFFFF, mx1, 1));
        mx1 = fmaxf(mx1, __shfl_xor_sync(0xFFFFFFFF, mx1, 2));
        float f0 = __expf(m0 - mx0), f1 = __expf(m1 - mx1);
        m0 = mx0; m1 = mx1;
        l0 *= f0;  l1 *= f1;
        #pragma unroll
        for (int nf = 0; nf < 8; nf++) {
            O[nf][0] *= f0; O[nf][1] *= f0;
            O[nf][2] *= f1; O[nf][3] *= f1;
        }

        // ---- P = exp(s - m), split into bf16 A-fragments ----
        uint32_t pah[4][4], pal[4][4];
        float rs0 = 0.f, rs1 = 0.f;
        #pragma unroll
        for (int ks = 0; ks < 4; ks++) {
            #pragma unroll
            for (int half = 0; half < 2; half++) {
                int nf = 2 * ks + half;
                float p0 = __expf(s[nf][0] - m0);
                float p1 = __expf(s[nf][1] - m0);
                float p2 = __expf(s[nf][2] - m1);
                float p3 = __expf(s[nf][3] - m1);
                rs0 += p0 + p1;
                rs1 += p2 + p3;
                __nv_bfloat16 h0 = __float2bfloat16(p0), h1 = __float2bfloat16(p1);
                __nv_bfloat16 h2 = __float2bfloat16(p2), h3 = __float2bfloat16(p3);
                pah[ks][0 + 2 * half] = packbf2(h0, h1);
                pah[ks][1 + 2 * half] = packbf2(h2, h3);
                pal[ks][0 + 2 * half] = packbf2(
                    __float2bfloat16(p0 - __bfloat162float(h0)),
                    __float2bfloat16(p1 - __bfloat162float(h1)));
                pal[ks][1 + 2 * half] = packbf2(
                    __float2bfloat16(p2 - __bfloat162float(h2)),
                    __float2bfloat16(p3 - __bfloat162float(h3)));
            }
        }
        rs0 += __shfl_xor_sync(0xFFFFFFFF, rs0, 1);
        rs0 += __shfl_xor_sync(0xFFFFFFFF, rs0, 2);
        rs1 += __shfl_xor_sync(0xFFFFFFFF, rs1, 1);
        rs1 += __shfl_xor_sync(0xFFFFFFFF, rs1, 2);
        l0 += rs0; l1 += rs1;

        // ---- O += P V ----
        #pragma unroll
        for (int ks = 0; ks < 4; ks++) {
            uint32_t vh[8][2], vl[8][2];
            int vrow = ks * 16 + (lane & 7) + ((lane >> 3) & 1) * 8;
            #pragma unroll
            for (int ng = 0; ng < 4; ng++) {
                uint32_t off = (uint32_t)(vrow * ATT_STRIDE + (ng * 16 + (lane >> 4) * 8) * 2);
                ldsm4t(vh[2 * ng][0], vh[2 * ng][1], vh[2 * ng + 1][0], vh[2 * ng + 1][1], sV + off);
                ldsm4t(vl[2 * ng][0], vl[2 * ng][1], vl[2 * ng + 1][0], vl[2 * ng + 1][1], sVl + off);
            }
            #pragma unroll
            for (int nf = 0; nf < 8; nf++) mma_bf16(O[nf], pah[ks], vh[nf]);
            #pragma unroll
            for (int nf = 0; nf < 8; nf++) mma_bf16(O[nf], pah[ks], vl[nf]);
            #pragma unroll
            for (int nf = 0; nf < 8; nf++) mma_bf16(O[nf], pal[ks], vh[nf]);
        }
        __syncthreads();
    }

    // ---- epilogue: normalize, split to bf16, write ctx into GEMM2 A buffers ----
    float inv0 = 1.f / l0, inv1 = 1.f / l1;
    int b = bh >> 4, h = bh & 15;
    int r0g = 128 * qt + w * 16 + (lane >> 2);
    #pragma unroll
    for (int nf = 0; nf < 8; nf++) {
        int d = h * 64 + nf * 8 + 2 * (lane & 3);
        size_t dst0 = (size_t)(b * SEQ + r0g) * 1024 + d;
        size_t dst1 = dst0 + (size_t)8 * 1024;
        float v0 = O[nf][0] * inv0, v1 = O[nf][1] * inv0;
        float v2 = O[nf][2] * inv1, v3 = O[nf][3] * inv1;
        __nv_bfloat16 h0 = __float2bfloat16(v0), h1 = __float2bfloat16(v1);
        __nv_bfloat16 h2 = __float2bfloat16(v2), h3 = __float2bfloat16(v3);
        *(__nv_bfloat162*)(g_Ahi + dst0) = __nv_bfloat162(h0, h1);
        *(__nv_bfloat162*)(g_Ahi + dst1) = __nv_bfloat162(h2, h3);
        *(__nv_bfloat162*)(g_Alo + dst0) = __nv_bfloat162(
            __float2bfloat16(v0 - __bfloat162float(h0)),
            __float2bfloat16(v1 - __bfloat162float(h1)));
        *(__nv_bfloat162*)(g_Alo + dst1) = __nv_bfloat162(
            __float2bfloat16(v2 - __bfloat162float(h2)),
            __float2bfloat16(v3 - __bfloat162float(h3)));
    }
}

// ---------------------------------------------------------------------------
extern "C" void kernel_launch(void* const* d_in, const int* in_sizes, int n_in,
                              void* d_out, int out_size)
{
    const float* y    = (const float*)d_in[0];
    const float* Wqkv = (const float*)d_in[1];
    const float* Wff  = (const float*)d_in[2];
    const float* bff  = (const float*)d_in[3];
    float* out = (float*)d_out;

    __nv_bfloat16 *ahi, *alo, *bhi, *blo;
    cudaGetSymbolAddress((void**)&ahi, g_Ahi);
    cudaGetSymbolAddress((void**)&alo, g_Alo);
    cudaGetSymbolAddress((void**)&bhi, g_Bhi);
    cudaGetSymbolAddress((void**)&blo, g_Blo);

    cudaFuncSetAttribute(hgemm128, cudaFuncAttributeMaxDynamicSharedMemorySize, HG_SMEM);
    cudaFuncSetAttribute(attn_mma, cudaFuncAttributeMaxDynamicSharedMemorySize, ATT_SMEM);

    // 1) split/transpose inputs
    tconv<<<dim3(3072 / 32, 1024 / 32), 256>>>(Wqkv, bhi, blo, 1024, 3072);
    sconv<<<(MTOT * 1024 / 4 + 255) / 256, 256>>>(y, ahi, alo, MTOT * 1024 / 4);

    // 2) qkv = y @ Wqkv -> split-bf16 Q/K/V head-major (mode 1)
    hgemm128<<<dim3(3072 / 128, MTOT / 128), 256, HG_SMEM>>>(
        ahi, alo, bhi, blo, nullptr, nullptr, 3072, 1024, 1);

    // 3) tensor-core causal attention -> ctx split-bf16 into A buffers
    attn_mma<<<dim3(SEQ / 128, 2 * NH), 256, ATT_SMEM>>>();

    // 4) out = ctx @ Wff + bff (mode 0)
    tconv<<<dim3(1024 / 32, 1024 / 32), 256>>>(Wff, bhi, blo, 1024, 1024);
    hgemm128<<<dim3(1024 / 128, MTOT / 128), 256, HG_SMEM>>>(
        ahi, alo, bhi, blo, bff, out, 1024, 1024, 0);
}